// round 3
// baseline (speedup 1.0000x reference)
#include <cuda_runtime.h>

// LUT tree: x (B,1024) -> t0(256,16) t1(64,16) t2(16,16) t3(4,16) t4(1,16) -> out (B,)
// G=4 rows per warp; lane l handles layer-0 nodes {32j+l}. Table regs loaded once
// per node-group j and reused across the 4 rows. Tables pre-differenced (a, b-a).
// R3 change: __launch_bounds__(256, 3) -> reg cap 85 -> 3 CTAs/SM (was 2 @ 96 regs).

#define G       4      // rows per warp
#define NWARPS  8
#define THREADS (NWARPS * 32)

// padded table layout: 20 floats per node (16 used + 4 pad) -> 80B stride,
// conflict-free LDS.128 across lanes
#define TPAD 20
#define OFF0 0
#define OFF1 (256 * TPAD)
#define OFF2 (OFF1 + 64 * TPAD)
#define OFF3 (OFF2 + 16 * TPAD)
#define OFF4 (OFF3 + 4 * TPAD)
#define TTOT (OFF4 + TPAD)                 // 6820 floats
#define XCHF (NWARPS * G * 256)            // exchange floats
#define SMEM_BYTES ((TTOT + XCHF) * 4)     // 60048 B

__device__ __forceinline__ float lerpf(float a, float b, float x) {
    return fmaf(x, b - a, a);
}

// tables pre-differenced: (a0,d0,a1,d1,...), d_k = corner(2k+1)-corner(2k)
__device__ __forceinline__ float node_eval_pd(float4 c0, float4 c1, float4 c2, float4 c3,
                                              float4 xv) {
    float v0 = fmaf(xv.x, c0.y, c0.x);
    float v1 = fmaf(xv.x, c0.w, c0.z);
    float v2 = fmaf(xv.x, c1.y, c1.x);
    float v3 = fmaf(xv.x, c1.w, c1.z);
    float v4 = fmaf(xv.x, c2.y, c2.x);
    float v5 = fmaf(xv.x, c2.w, c2.z);
    float v6 = fmaf(xv.x, c3.y, c3.x);
    float v7 = fmaf(xv.x, c3.w, c3.z);
    float w0 = lerpf(v0, v1, xv.y);
    float w1 = lerpf(v2, v3, xv.y);
    float w2 = lerpf(v4, v5, xv.y);
    float w3 = lerpf(v6, v7, xv.y);
    float z0 = lerpf(w0, w1, xv.z);
    float z1 = lerpf(w2, w3, xv.z);
    return lerpf(z0, z1, xv.w);
}

__device__ __forceinline__ float node_eval_sh(const float* t, float4 xv) {
    float4 c0 = *(const float4*)(t + 0);
    float4 c1 = *(const float4*)(t + 4);
    float4 c2 = *(const float4*)(t + 8);
    float4 c3 = *(const float4*)(t + 12);
    return node_eval_pd(c0, c1, c2, c3, xv);
}

__global__ void __launch_bounds__(THREADS, 3) lut_tree_kernel(
    const float* __restrict__ x,
    const float* __restrict__ t0, const float* __restrict__ t1,
    const float* __restrict__ t2, const float* __restrict__ t3,
    const float* __restrict__ t4,
    float* __restrict__ out, int n_rows)
{
    extern __shared__ __align__(16) float smem[];
    float* sh_t = smem;            // TTOT floats, pre-differenced padded tables
    float* sh_x = smem + TTOT;     // [NWARPS][G][256] exchange

    // cooperative pre-differenced table load: element pairs (a, b-a)
    {
        const float* tabs[5] = {t0, t1, t2, t3, t4};
        const int nn[5] = {256, 64, 16, 4, 1};
        int off = 0;
        #pragma unroll
        for (int L = 0; L < 5; ++L) {
            int npairs = nn[L] * 8;
            for (int p = threadIdx.x; p < npairs; p += THREADS) {
                int node = p >> 3, k = p & 7;
                float a = tabs[L][node * 16 + 2 * k];
                float b = tabs[L][node * 16 + 2 * k + 1];
                sh_t[off + node * TPAD + 2 * k]     = a;
                sh_t[off + node * TPAD + 2 * k + 1] = b - a;
            }
            off += nn[L] * TPAD;
        }
    }
    __syncthreads();

    const int warp = threadIdx.x >> 5;
    const int lane = threadIdx.x & 31;
    const int row0 = (blockIdx.x * NWARPS + warp) * G;

    float* xch = sh_x + warp * (G * 256);

    // ---- layer 0: j-outer so table regs are reused across G rows ----
    #pragma unroll
    for (int j = 0; j < 8; ++j) {
        float4 Xr[G];
        #pragma unroll
        for (int r = 0; r < G; ++r)
            Xr[r] = ((const float4*)(x + (size_t)(row0 + r) * 1024))[j * 32 + lane];

        const float* tp = &sh_t[OFF0 + (j * 32 + lane) * TPAD];
        float4 c0 = *(const float4*)(tp + 0);
        float4 c1 = *(const float4*)(tp + 4);
        float4 c2 = *(const float4*)(tp + 8);
        float4 c3 = *(const float4*)(tp + 12);

        #pragma unroll
        for (int r = 0; r < G; ++r)
            xch[r * 256 + j * 32 + lane] = node_eval_pd(c0, c1, c2, c3, Xr[r]);
    }
    __syncwarp();

    const unsigned FULL = 0xffffffffu;

    // ---- layers 1..4 per row ----
    #pragma unroll
    for (int r = 0; r < G; ++r) {
        // layer 1: 64 nodes; lane computes nodes 2*lane, 2*lane+1
        float4 a0 = *(const float4*)&xch[r * 256 + lane * 8];
        float4 a1 = *(const float4*)&xch[r * 256 + lane * 8 + 4];
        float z0 = node_eval_sh(&sh_t[OFF1 + (2 * lane) * TPAD], a0);
        float z1 = node_eval_sh(&sh_t[OFF1 + (2 * lane + 1) * TPAD], a1);

        // layer 2: 16 nodes; lane l (mod 16) computes node l
        float4 b;
        b.x = __shfl_sync(FULL, z0, (lane * 2) & 31);
        b.y = __shfl_sync(FULL, z1, (lane * 2) & 31);
        b.z = __shfl_sync(FULL, z0, (lane * 2 + 1) & 31);
        b.w = __shfl_sync(FULL, z1, (lane * 2 + 1) & 31);
        float w = node_eval_sh(&sh_t[OFF2 + (lane & 15) * TPAD], b);

        // layer 3: 4 nodes
        float4 c;
        c.x = __shfl_sync(FULL, w, (lane * 4 + 0) & 31);
        c.y = __shfl_sync(FULL, w, (lane * 4 + 1) & 31);
        c.z = __shfl_sync(FULL, w, (lane * 4 + 2) & 31);
        c.w = __shfl_sync(FULL, w, (lane * 4 + 3) & 31);
        float v = node_eval_sh(&sh_t[OFF3 + (lane & 3) * TPAD], c);

        // layer 4: 1 node from lanes 0..3
        float4 d;
        d.x = __shfl_sync(FULL, v, 0);
        d.y = __shfl_sync(FULL, v, 1);
        d.z = __shfl_sync(FULL, v, 2);
        d.w = __shfl_sync(FULL, v, 3);
        if (lane == 0 && row0 + r < n_rows)
            out[row0 + r] = node_eval_sh(&sh_t[OFF4], d);
    }
}

extern "C" void kernel_launch(void* const* d_in, const int* in_sizes, int n_in,
                              void* d_out, int out_size) {
    const float* x  = (const float*)d_in[0];
    const float* t0 = (const float*)d_in[1];
    const float* t1 = (const float*)d_in[2];
    const float* t2 = (const float*)d_in[3];
    const float* t3 = (const float*)d_in[4];
    const float* t4 = (const float*)d_in[5];
    float* out = (float*)d_out;

    int n_rows = in_sizes[0] / 1024;                 // 32768
    int rows_per_block = NWARPS * G;                 // 32
    int grid = (n_rows + rows_per_block - 1) / rows_per_block;

    cudaFuncSetAttribute(lut_tree_kernel,
                         cudaFuncAttributeMaxDynamicSharedMemorySize, SMEM_BYTES);
    lut_tree_kernel<<<grid, THREADS, SMEM_BYTES>>>(x, t0, t1, t2, t3, t4, out, n_rows);
}

// round 4
// speedup vs baseline: 1.0883x; 1.0883x over previous
#include <cuda_runtime.h>

// LUT tree: x (B,1024) -> t0(256,16) t1(64,16) t2(16,16) t3(4,16) t4(1,16) -> out (B,)
// G=8 rows per warp, 2 CTAs/SM (128-reg budget). Layer-0 j-loop double-buffers the
// x loads: 8 independent LDG.128 (32 cache lines) in flight per warp while the
// previous batch computes. Tables pre-differenced (a, b-a) in padded shared.

#define G       8      // rows per warp
#define NWARPS  8
#define THREADS (NWARPS * 32)

// padded table layout: 20 floats per node (16 used + 4 pad) -> 80B stride,
// conflict-free LDS.128 across lanes
#define TPAD 20
#define OFF0 0
#define OFF1 (256 * TPAD)
#define OFF2 (OFF1 + 64 * TPAD)
#define OFF3 (OFF2 + 16 * TPAD)
#define OFF4 (OFF3 + 4 * TPAD)
#define TTOT (OFF4 + TPAD)                 // 6820 floats (27280 B)
#define XCHF (NWARPS * G * 256)            // 16384 floats (65536 B)
#define SMEM_BYTES ((TTOT + XCHF) * 4)     // 92816 B

__device__ __forceinline__ float lerpf(float a, float b, float x) {
    return fmaf(x, b - a, a);
}

// tables pre-differenced: (a0,d0,a1,d1,...), d_k = corner(2k+1)-corner(2k)
__device__ __forceinline__ float node_eval_pd(float4 c0, float4 c1, float4 c2, float4 c3,
                                              float4 xv) {
    float v0 = fmaf(xv.x, c0.y, c0.x);
    float v1 = fmaf(xv.x, c0.w, c0.z);
    float v2 = fmaf(xv.x, c1.y, c1.x);
    float v3 = fmaf(xv.x, c1.w, c1.z);
    float v4 = fmaf(xv.x, c2.y, c2.x);
    float v5 = fmaf(xv.x, c2.w, c2.z);
    float v6 = fmaf(xv.x, c3.y, c3.x);
    float v7 = fmaf(xv.x, c3.w, c3.z);
    float w0 = lerpf(v0, v1, xv.y);
    float w1 = lerpf(v2, v3, xv.y);
    float w2 = lerpf(v4, v5, xv.y);
    float w3 = lerpf(v6, v7, xv.y);
    float z0 = lerpf(w0, w1, xv.z);
    float z1 = lerpf(w2, w3, xv.z);
    return lerpf(z0, z1, xv.w);
}

__device__ __forceinline__ float node_eval_sh(const float* t, float4 xv) {
    float4 c0 = *(const float4*)(t + 0);
    float4 c1 = *(const float4*)(t + 4);
    float4 c2 = *(const float4*)(t + 8);
    float4 c3 = *(const float4*)(t + 12);
    return node_eval_pd(c0, c1, c2, c3, xv);
}

__global__ void __launch_bounds__(THREADS, 2) lut_tree_kernel(
    const float* __restrict__ x,
    const float* __restrict__ t0, const float* __restrict__ t1,
    const float* __restrict__ t2, const float* __restrict__ t3,
    const float* __restrict__ t4,
    float* __restrict__ out, int n_rows)
{
    extern __shared__ __align__(16) float smem[];
    float* sh_t = smem;            // TTOT floats, pre-differenced padded tables
    float* sh_x = smem + TTOT;     // [NWARPS][G][256] exchange

    // cooperative pre-differenced table load: element pairs (a, b-a)
    {
        const float* tabs[5] = {t0, t1, t2, t3, t4};
        const int nn[5] = {256, 64, 16, 4, 1};
        int off = 0;
        #pragma unroll
        for (int L = 0; L < 5; ++L) {
            int npairs = nn[L] * 8;
            for (int p = threadIdx.x; p < npairs; p += THREADS) {
                int node = p >> 3, k = p & 7;
                float a = tabs[L][node * 16 + 2 * k];
                float b = tabs[L][node * 16 + 2 * k + 1];
                sh_t[off + node * TPAD + 2 * k]     = a;
                sh_t[off + node * TPAD + 2 * k + 1] = b - a;
            }
            off += nn[L] * TPAD;
        }
    }
    __syncthreads();

    const int warp = threadIdx.x >> 5;
    const int lane = threadIdx.x & 31;
    const int row0 = (blockIdx.x * NWARPS + warp) * G;

    float* xch = sh_x + warp * (G * 256);
    const float4* xbase = (const float4*)(x + (size_t)row0 * 1024);

    // ---- layer 0: j-outer, double-buffered x loads across j ----
    float4 Xc[G];
    #pragma unroll
    for (int r = 0; r < G; ++r)
        Xc[r] = xbase[r * 256 + lane];          // j=0 batch (float4 row stride 256)

    #pragma unroll
    for (int j = 0; j < 8; ++j) {
        float4 Xn[G];
        if (j < 7) {
            #pragma unroll
            for (int r = 0; r < G; ++r)
                Xn[r] = xbase[r * 256 + (j + 1) * 32 + lane];
        }

        const float* tp = &sh_t[OFF0 + (j * 32 + lane) * TPAD];
        float4 c0 = *(const float4*)(tp + 0);
        float4 c1 = *(const float4*)(tp + 4);
        float4 c2 = *(const float4*)(tp + 8);
        float4 c3 = *(const float4*)(tp + 12);

        #pragma unroll
        for (int r = 0; r < G; ++r)
            xch[r * 256 + j * 32 + lane] = node_eval_pd(c0, c1, c2, c3, Xc[r]);

        if (j < 7) {
            #pragma unroll
            for (int r = 0; r < G; ++r) Xc[r] = Xn[r];
        }
    }
    __syncwarp();

    const unsigned FULL = 0xffffffffu;

    // ---- layers 1..4 per row ----
    #pragma unroll
    for (int r = 0; r < G; ++r) {
        // layer 1: 64 nodes; lane computes nodes 2*lane, 2*lane+1
        float4 a0 = *(const float4*)&xch[r * 256 + lane * 8];
        float4 a1 = *(const float4*)&xch[r * 256 + lane * 8 + 4];
        float z0 = node_eval_sh(&sh_t[OFF1 + (2 * lane) * TPAD], a0);
        float z1 = node_eval_sh(&sh_t[OFF1 + (2 * lane + 1) * TPAD], a1);

        // layer 2: 16 nodes; lane l (mod 16) computes node l
        float4 b;
        b.x = __shfl_sync(FULL, z0, (lane * 2) & 31);
        b.y = __shfl_sync(FULL, z1, (lane * 2) & 31);
        b.z = __shfl_sync(FULL, z0, (lane * 2 + 1) & 31);
        b.w = __shfl_sync(FULL, z1, (lane * 2 + 1) & 31);
        float w = node_eval_sh(&sh_t[OFF2 + (lane & 15) * TPAD], b);

        // layer 3: 4 nodes
        float4 c;
        c.x = __shfl_sync(FULL, w, (lane * 4 + 0) & 31);
        c.y = __shfl_sync(FULL, w, (lane * 4 + 1) & 31);
        c.z = __shfl_sync(FULL, w, (lane * 4 + 2) & 31);
        c.w = __shfl_sync(FULL, w, (lane * 4 + 3) & 31);
        float v = node_eval_sh(&sh_t[OFF3 + (lane & 3) * TPAD], c);

        // layer 4: 1 node from lanes 0..3
        float4 d;
        d.x = __shfl_sync(FULL, v, 0);
        d.y = __shfl_sync(FULL, v, 1);
        d.z = __shfl_sync(FULL, v, 2);
        d.w = __shfl_sync(FULL, v, 3);
        if (lane == 0 && row0 + r < n_rows)
            out[row0 + r] = node_eval_sh(&sh_t[OFF4], d);
    }
}

extern "C" void kernel_launch(void* const* d_in, const int* in_sizes, int n_in,
                              void* d_out, int out_size) {
    const float* x  = (const float*)d_in[0];
    const float* t0 = (const float*)d_in[1];
    const float* t1 = (const float*)d_in[2];
    const float* t2 = (const float*)d_in[3];
    const float* t3 = (const float*)d_in[4];
    const float* t4 = (const float*)d_in[5];
    float* out = (float*)d_out;

    int n_rows = in_sizes[0] / 1024;                 // 32768
    int rows_per_block = NWARPS * G;                 // 64
    int grid = (n_rows + rows_per_block - 1) / rows_per_block;

    cudaFuncSetAttribute(lut_tree_kernel,
                         cudaFuncAttributeMaxDynamicSharedMemorySize, SMEM_BYTES);
    lut_tree_kernel<<<grid, THREADS, SMEM_BYTES>>>(x, t0, t1, t2, t3, t4, out, n_rows);
}